// round 14
// baseline (speedup 1.0000x reference)
#include <cuda_runtime.h>
#include <math.h>
#include <stdint.h>

#define NB_   1024
#define NS    500
#define RG    128
#define NLAT  12
#define NFEAT 64
#define NHID  128
#define NPTS  (NB_*NS)
#define NROW  21          // 9 raw inputs + 12 folded latents
#define KTC   24          // K padded for tensor cores (3 x k8)
#define MTILE 64          // points per block tile
#define APAD  72          // sA row pitch (bank = 8k+r, conflict-free)
#define WPAD  136         // sW row pitch (bank = 8k+j, conflict-free)

// Scratch (static device arrays: no allocation allowed)
__device__ float4 g_rgbs[NPTS];          // (r, g, b, sdf) - active entries only
__device__ float  g_W1eff[NLAT*NHID];    // folded Wf @ W1[9:73]
__device__ float  g_b1eff[NHID];         // b1 + bf @ W1[9:73]
__device__ int    g_act_list[NPTS];      // packed (ray<<9)|s for active samples
__device__ int    g_slo[NB_];            // first active s per ray
__device__ int    g_scnt[NB_];           // active count per ray
__device__ int    g_total;               // total active samples
__device__ float  g_inT[22*NPTS];        // transposed MLP inputs: [k][i], k=21 is sdf

// ---- tf32 helpers ---------------------------------------------------------
__device__ __forceinline__ float tf32_rna(float x) {
    uint32_t u;
    asm("cvt.rna.tf32.f32 %0, %1;" : "=r"(u) : "f"(x));
    return __uint_as_float(u);
}
__device__ __forceinline__ void mma_tf32(float* d, const uint32_t* a,
                                         const uint32_t* b) {
    asm("mma.sync.aligned.m16n8k8.row.col.f32.tf32.tf32.f32 "
        "{%0,%1,%2,%3}, {%4,%5,%6,%7}, {%8,%9}, {%0,%1,%2,%3};"
        : "+f"(d[0]), "+f"(d[1]), "+f"(d[2]), "+f"(d[3])
        : "r"(a[0]), "r"(a[1]), "r"(a[2]), "r"(a[3]), "r"(b[0]), "r"(b[1]));
}

// ---------------------------------------------------------------------------
__global__ __launch_bounds__(256)
void prep_kernel(const float* __restrict__ Wf,
                 const float* __restrict__ bf,
                 const float* __restrict__ W1,
                 const float* __restrict__ b1)
{
    int tid = threadIdx.x;
    if (tid == 0) g_total = 0;
    for (int e = tid; e < NLAT*NHID; e += 256) {
        int l = e >> 7, j = e & 127;
        float acc = 0.f;
        #pragma unroll 8
        for (int f = 0; f < NFEAT; f++)
            acc = fmaf(Wf[l*NFEAT + f], W1[(9+f)*NHID + j], acc);
        g_W1eff[e] = acc;
    }
    for (int j = tid; j < NHID; j += 256) {
        float acc = b1[j];
        #pragma unroll 8
        for (int f = 0; f < NFEAT; f++)
            acc = fmaf(bf[f], W1[(9+f)*NHID + j], acc);
        g_b1eff[j] = acc;
    }
}

// ---------------------------------------------------------------------------
// interval_kernel: one warp per ray; ballot -> contiguous [first,last], compact.
// ---------------------------------------------------------------------------
__global__ __launch_bounds__(256)
void interval_kernel(const float* __restrict__ rays_o,
                     const float* __restrict__ rays_d)
{
    int warp = (blockIdx.x*blockDim.x + threadIdx.x) >> 5;
    int lane = threadIdx.x & 31;
    if (warp >= NB_) return;
    int ray = warp;

    float ox = __ldg(&rays_o[3*ray+0]), oy = __ldg(&rays_o[3*ray+1]),
          oz = __ldg(&rays_o[3*ray+2]);
    float dx = __ldg(&rays_d[3*ray+0]), dy = __ldg(&rays_d[3*ray+1]),
          dz = __ldg(&rays_d[3*ray+2]);

    int first = -1, last = -1;
    #pragma unroll
    for (int c = 0; c < 16; c++) {
        int s = c*32 + lane;
        float z  = 0.5f + 3.0f*((float)s * (1.0f/499.0f));
        float px = fmaf(dx, z, ox), py = fmaf(dy, z, oy), pz = fmaf(dz, z, oz);
        bool act = (s < NS) &
                   (px >= -1.f) & (px <= 1.f) &
                   (py >= -1.f) & (py <= 1.f) &
                   (pz >= -1.f) & (pz <= 1.f);
        unsigned m = __ballot_sync(0xffffffffu, act);
        if (m) {
            if (first < 0) first = c*32 + (__ffs(m) - 1);
            last = c*32 + (31 - __clz(m));
        }
    }
    int cnt = (first >= 0) ? (last - first + 1) : 0;

    int off = 0;
    if (lane == 0) {
        g_slo[ray]  = first;
        g_scnt[ray] = cnt;
        if (cnt > 0) off = atomicAdd(&g_total, cnt);
    }
    off = __shfl_sync(0xffffffffu, off, 0);

    if (cnt > 0) {
        for (int s = first + lane; s <= last; s += 32)
            g_act_list[off + (s - first)] = (ray << 9) | s;
    }
}

// ---------------------------------------------------------------------------
// Kernel T: trilerp + grad, one point per thread, HIGH occupancy.
// Writes transposed inputs g_inT[k][i] (coalesced per k) + sdf at k=21.
// ---------------------------------------------------------------------------
__global__ __launch_bounds__(128, 8)
void trilerp_kernel(const float* __restrict__ rays_o,
                    const float* __restrict__ rays_d,
                    const float* __restrict__ viewdirs,
                    const float* __restrict__ grid)
{
    const int OX = RG*RG*13, OY = RG*13, OZ = 13;
    int total  = g_total;
    int gid    = blockIdx.x*blockDim.x + threadIdx.x;
    int stride = gridDim.x*blockDim.x;

    for (int i = gid; i < total; i += stride) {
        int ia = g_act_list[i];
        int r = ia >> 9, s = ia & 511;

        float z  = 0.5f + 3.0f*((float)s * (1.0f/499.0f));
        float px = fmaf(__ldg(&rays_d[3*r+0]), z, __ldg(&rays_o[3*r+0]));
        float py = fmaf(__ldg(&rays_d[3*r+1]), z, __ldg(&rays_o[3*r+1]));
        float pz = fmaf(__ldg(&rays_d[3*r+2]), z, __ldg(&rays_o[3*r+2]));

        float ux = (px + 1.f)*63.5f, uy = (py + 1.f)*63.5f, uz = (pz + 1.f)*63.5f;
        int ix = min((int)ux, 126), iy = min((int)uy, 126), iz = min((int)uz, 126);
        float fx = ux - (float)ix, fy = uy - (float)iy, fz = uz - (float)iz;
        float wx0 = 1.f-fx, wx1 = fx, wy0 = 1.f-fy, wy1 = fy,
              wz0 = 1.f-fz, wz1 = fz;

        const float* gp = grid + ((size_t)(ix*RG + iy)*RG + iz)*13;

        float vals[13];
        #pragma unroll
        for (int c = 0; c < 13; c++) vals[c] = 0.f;
        float c0a[8];
        #pragma unroll
        for (int cc = 0; cc < 8; cc++) {
            int dx = cc >> 2, dy = (cc >> 1) & 1, dz = cc & 1;
            const float* p = gp + dx*OX + dy*OY + dz*OZ;
            float w = (dx ? wx1 : wx0) * (dy ? wy1 : wy0) * (dz ? wz1 : wz0);
            float v0 = __ldg(p);
            c0a[cc] = v0;
            vals[0] = fmaf(w, v0, vals[0]);
            #pragma unroll
            for (int c = 1; c < 13; c++) vals[c] = fmaf(w, __ldg(p + c), vals[c]);
        }
        float gx = 63.5f*( wy0*wz0*(c0a[4]-c0a[0]) + wy0*wz1*(c0a[5]-c0a[1])
                         + wy1*wz0*(c0a[6]-c0a[2]) + wy1*wz1*(c0a[7]-c0a[3]) );
        float gy = 63.5f*( wx0*wz0*(c0a[2]-c0a[0]) + wx0*wz1*(c0a[3]-c0a[1])
                         + wx1*wz0*(c0a[6]-c0a[4]) + wx1*wz1*(c0a[7]-c0a[5]) );
        float gz = 63.5f*( wx0*wy0*(c0a[1]-c0a[0]) + wx0*wy1*(c0a[3]-c0a[2])
                         + wx1*wy0*(c0a[5]-c0a[4]) + wx1*wy1*(c0a[7]-c0a[6]) );

        g_inT[ 0*NPTS + i] = px;
        g_inT[ 1*NPTS + i] = py;
        g_inT[ 2*NPTS + i] = pz;
        g_inT[ 3*NPTS + i] = gx;
        g_inT[ 4*NPTS + i] = gy;
        g_inT[ 5*NPTS + i] = gz;
        g_inT[ 6*NPTS + i] = __ldg(&viewdirs[3*r+0]);
        g_inT[ 7*NPTS + i] = __ldg(&viewdirs[3*r+1]);
        g_inT[ 8*NPTS + i] = __ldg(&viewdirs[3*r+2]);
        #pragma unroll
        for (int l = 0; l < NLAT; l++)
            g_inT[(9+l)*NPTS + i] = vals[1+l];
        g_inT[21*NPTS + i] = vals[0];
    }
}

// ---------------------------------------------------------------------------
// Kernel M: tensor-core MLP. mma.sync m16n8k8 tf32 with 3xTF32 hi/lo split.
// Block 128 thr (4 warps); tile 64 pts x 128 hidden; K=24 (3 k8 steps).
// ---------------------------------------------------------------------------
__global__ __launch_bounds__(128, 4)
void mlp_kernel(const float* __restrict__ W1,
                const float* __restrict__ W2,
                const float* __restrict__ b2)
{
    __shared__ __align__(16) float sAhi[KTC*APAD];
    __shared__ __align__(16) float sAlo[KTC*APAD];
    __shared__ __align__(16) float sWhi[KTC*WPAD];
    __shared__ __align__(16) float sWlo[KTC*WPAD];
    __shared__ __align__(16) float sW2t[3*NHID];     // [c][j]
    __shared__ __align__(16) float sb1[NHID];
    __shared__ float sb2[4];

    int tid = threadIdx.x;
    // W hi/lo split (rows 0-8 raw, 9-20 folded, 21-23 zero)
    for (int e = tid; e < KTC*NHID; e += 128) {
        int k = e >> 7, j = e & 127;
        float v = 0.f;
        if (k < 9)          v = W1[k*NHID + j];
        else if (k < NROW)  v = g_W1eff[(k-9)*NHID + j];
        float h = tf32_rna(v);
        sWhi[k*WPAD + j] = h;
        sWlo[k*WPAD + j] = tf32_rna(v - h);
    }
    for (int i = tid; i < NHID; i += 128) sb1[i] = g_b1eff[i];
    for (int i = tid; i < NHID*3; i += 128) {
        int j = i / 3, c = i - 3*j;
        sW2t[c*NHID + j] = W2[i];
    }
    if (tid < 3) sb2[tid] = b2[tid];

    int total = g_total;
    int warpM = tid >> 5;
    int lane  = tid & 31;
    int qid   = lane >> 2;   // 0..7
    int tig   = lane & 3;    // 0..3

    for (int base = blockIdx.x*MTILE; base < total; base += gridDim.x*MTILE) {
        __syncthreads();   // protect sA (also orders weight init on 1st iter)
        for (int e = tid; e < KTC*MTILE; e += 128) {
            int k = e >> 6, p = e & 63;
            int i = base + p;
            float v = (k < NROW && i < total) ? g_inT[k*NPTS + i] : 0.f;
            float h = tf32_rna(v);
            sAhi[k*APAD + p] = h;
            sAlo[k*APAD + p] = tf32_rna(v - h);
        }
        __syncthreads();

        float acc[16][4];
        #pragma unroll
        for (int nb = 0; nb < 16; nb++)
            #pragma unroll
            for (int q = 0; q < 4; q++) acc[nb][q] = 0.f;

        #pragma unroll
        for (int ks = 0; ks < 3; ks++) {
            int k0 = ks*8 + tig, k1 = k0 + 4;
            int r0 = warpM*16 + qid;
            uint32_t ah[4], al[4];
            ah[0] = __float_as_uint(sAhi[k0*APAD + r0]);
            ah[1] = __float_as_uint(sAhi[k0*APAD + r0 + 8]);
            ah[2] = __float_as_uint(sAhi[k1*APAD + r0]);
            ah[3] = __float_as_uint(sAhi[k1*APAD + r0 + 8]);
            al[0] = __float_as_uint(sAlo[k0*APAD + r0]);
            al[1] = __float_as_uint(sAlo[k0*APAD + r0 + 8]);
            al[2] = __float_as_uint(sAlo[k1*APAD + r0]);
            al[3] = __float_as_uint(sAlo[k1*APAD + r0 + 8]);
            #pragma unroll
            for (int nb = 0; nb < 16; nb++) {
                int jb = nb*8 + qid;
                uint32_t bh[2], bl[2];
                bh[0] = __float_as_uint(sWhi[k0*WPAD + jb]);
                bh[1] = __float_as_uint(sWhi[k1*WPAD + jb]);
                bl[0] = __float_as_uint(sWlo[k0*WPAD + jb]);
                bl[1] = __float_as_uint(sWlo[k1*WPAD + jb]);
                mma_tf32(acc[nb], ah, bh);
                mma_tf32(acc[nb], ah, bl);
                mma_tf32(acc[nb], al, bh);
            }
        }

        // epilogue: bias+relu, fold W2, quad-reduce over tig, sigmoid, store
        float o0a = 0.f, o1a = 0.f, o2a = 0.f;   // point row r
        float o0b = 0.f, o1b = 0.f, o2b = 0.f;   // point row r+8
        #pragma unroll
        for (int nb = 0; nb < 16; nb++) {
            int j0 = nb*8 + 2*tig, j1 = j0 + 1;
            float bj0 = sb1[j0], bj1 = sb1[j1];
            float h00 = fmaxf(acc[nb][0] + bj0, 0.f);
            float h01 = fmaxf(acc[nb][1] + bj1, 0.f);
            float h10 = fmaxf(acc[nb][2] + bj0, 0.f);
            float h11 = fmaxf(acc[nb][3] + bj1, 0.f);
            float w00 = sW2t[0*NHID + j0], w01 = sW2t[0*NHID + j1];
            float w10 = sW2t[1*NHID + j0], w11 = sW2t[1*NHID + j1];
            float w20 = sW2t[2*NHID + j0], w21 = sW2t[2*NHID + j1];
            o0a = fmaf(h00, w00, fmaf(h01, w01, o0a));
            o1a = fmaf(h00, w10, fmaf(h01, w11, o1a));
            o2a = fmaf(h00, w20, fmaf(h01, w21, o2a));
            o0b = fmaf(h10, w00, fmaf(h11, w01, o0b));
            o1b = fmaf(h10, w10, fmaf(h11, w11, o1b));
            o2b = fmaf(h10, w20, fmaf(h11, w21, o2b));
        }
        #pragma unroll
        for (int off = 1; off <= 2; off <<= 1) {
            o0a += __shfl_xor_sync(0xffffffffu, o0a, off);
            o1a += __shfl_xor_sync(0xffffffffu, o1a, off);
            o2a += __shfl_xor_sync(0xffffffffu, o2a, off);
            o0b += __shfl_xor_sync(0xffffffffu, o0b, off);
            o1b += __shfl_xor_sync(0xffffffffu, o1b, off);
            o2b += __shfl_xor_sync(0xffffffffu, o2b, off);
        }
        if (tig == 0) {
            int i1 = base + warpM*16 + qid;
            int i2 = i1 + 8;
            if (i1 < total) {
                float sdf = __ldg(&g_inT[21*NPTS + i1]);
                int pa = g_act_list[i1];
                g_rgbs[(pa >> 9)*NS + (pa & 511)] =
                    make_float4(1.f/(1.f + expf(-(o0a + sb2[0]))),
                                1.f/(1.f + expf(-(o1a + sb2[1]))),
                                1.f/(1.f + expf(-(o2a + sb2[2]))), sdf);
            }
            if (i2 < total) {
                float sdf = __ldg(&g_inT[21*NPTS + i2]);
                int pa = g_act_list[i2];
                g_rgbs[(pa >> 9)*NS + (pa & 511)] =
                    make_float4(1.f/(1.f + expf(-(o0b + sb2[0]))),
                                1.f/(1.f + expf(-(o1b + sb2[1]))),
                                1.f/(1.f + expf(-(o2b + sb2[2]))), sdf);
            }
        }
    }
}

// ---------------------------------------------------------------------------
// Kernel B: per-ray transmittance scan. One warp (=one block) per ray.
// ---------------------------------------------------------------------------
__global__ __launch_bounds__(32)
void ray_kernel(const float* __restrict__ rays_d,
                const float* __restrict__ beta_p,
                float* __restrict__ out)
{
    int ray  = blockIdx.x;
    int lane = threadIdx.x;

    float be    = fabsf(__ldg(beta_p)) + 1e-4f;
    float inv_b = 1.0f / be;
    float d0 = __ldg(&rays_d[3*ray+0]);
    float d1 = __ldg(&rays_d[3*ray+1]);
    float d2 = __ldg(&rays_d[3*ray+2]);
    float dn = sqrtf(d0*d0 + d1*d1 + d2*d2);

    int slo = g_slo[ray];
    int scnt = g_scnt[ray];
    int shi = slo + scnt;

    const float4* vp = g_rgbs + (size_t)ray*NS;
    const float dist = 3.0f/499.0f;

    float4 v[16];
    #pragma unroll
    for (int c = 0; c < 16; c++) {
        int s = c*32 + lane;
        bool in = (scnt > 0) & (s >= slo) & (s < shi) & (s < NS);
        v[c] = in ? __ldg(&vp[s]) : make_float4(0.f, 0.f, 0.f, 100.f);
    }

    float fe[16];
    #pragma unroll
    for (int c = 0; c < 16; c++) {
        float sdf = v[c].w;
        float as  = fabsf(sdf);
        float sg  = (sdf > 0.f) ? 1.f : ((sdf < 0.f) ? -1.f : 0.f);
        float dens = inv_b * (0.5f + 0.5f*sg*expm1f(-as*inv_b));
        fe[c] = dist * dens;
    }

    float inc[16];
    #pragma unroll
    for (int c = 0; c < 16; c++) {
        float x = fe[c];
        #pragma unroll
        for (int o = 1; o < 32; o <<= 1) {
            float n = __shfl_up_sync(0xffffffffu, x, o);
            if (lane >= o) x += n;
        }
        inc[c] = x;
    }

    float carry = 0.f, r0 = 0.f, r1 = 0.f, r2 = 0.f, dep = 0.f;
    #pragma unroll
    for (int c = 0; c < 16; c++) {
        float excl  = carry + (inc[c] - fe[c]);
        float T     = expf(-excl);
        float alpha = 1.f - expf(-fe[c]);
        float w     = alpha * T;
        int   s     = c*32 + lane;
        float zs    = 0.5f + 3.0f*((float)s * (1.0f/499.0f));
        if (s < NS) {
            r0  += w * v[c].x;
            r1  += w * v[c].y;
            r2  += w * v[c].z;
            dep += w * zs * dn;
        }
        carry += __shfl_sync(0xffffffffu, inc[c], 31);
    }

    #pragma unroll
    for (int o = 16; o > 0; o >>= 1) {
        r0  += __shfl_xor_sync(0xffffffffu, r0,  o);
        r1  += __shfl_xor_sync(0xffffffffu, r1,  o);
        r2  += __shfl_xor_sync(0xffffffffu, r2,  o);
        dep += __shfl_xor_sync(0xffffffffu, dep, o);
    }
    if (lane == 0) {
        out[3*ray+0]     = r0;
        out[3*ray+1]     = r1;
        out[3*ray+2]     = r2;
        out[3*NB_ + ray] = dep;
    }
}

// ---------------------------------------------------------------------------
extern "C" void kernel_launch(void* const* d_in, const int* in_sizes, int n_in,
                              void* d_out, int out_size)
{
    const float* rays_o   = (const float*)d_in[0];
    const float* rays_d   = (const float*)d_in[1];
    const float* viewdirs = (const float*)d_in[2];
    const float* grid     = (const float*)d_in[3];
    const float* Wf       = (const float*)d_in[4];
    const float* bf       = (const float*)d_in[5];
    const float* W1       = (const float*)d_in[6];
    const float* b1       = (const float*)d_in[7];
    const float* W2       = (const float*)d_in[8];
    const float* b2       = (const float*)d_in[9];
    const float* beta     = (const float*)d_in[10];

    // ncu captures our 0-based launch index 3 -> mlp_kernel there.
    prep_kernel<<<1, 256>>>(Wf, bf, W1, b1);                 // resets g_total
    interval_kernel<<<NB_/8, 256>>>(rays_o, rays_d);
    trilerp_kernel<<<1184, 128>>>(rays_o, rays_d, viewdirs, grid);
    mlp_kernel<<<740, 128>>>(W1, W2, b2);
    ray_kernel<<<NB_, 32>>>(rays_d, beta, (float*)d_out);
}

// round 15
// speedup vs baseline: 1.1672x; 1.1672x over previous
#include <cuda_runtime.h>
#include <math.h>
#include <stdint.h>

#define NB_   1024
#define NS    500
#define RG    128
#define NLAT  12
#define NFEAT 64
#define NHID  128
#define NPTS  (NB_*NS)
#define NROW  21          // 9 raw inputs + 12 folded latents
#define MTILE 64          // points per block tile

// Scratch (static device arrays: no allocation allowed)
__device__ float4 g_rgbs[NPTS];          // (r, g, b, sdf) - active entries only
__device__ float  g_W1eff[NLAT*NHID];    // folded Wf @ W1[9:73]
__device__ float  g_b1eff[NHID];         // b1 + bf @ W1[9:73]
__device__ int    g_act_list[NPTS];      // packed (ray<<9)|s for active samples
__device__ int    g_slo[NB_];            // first active s per ray
__device__ int    g_scnt[NB_];           // active count per ray
__device__ int    g_total;               // total active samples
__device__ float  g_inT[22*NPTS];        // transposed MLP inputs: [k][i], k=21 is sdf

// ---- tf32 helpers ---------------------------------------------------------
__device__ __forceinline__ float tf32_rna(float x) {
    uint32_t u;
    asm("cvt.rna.tf32.f32 %0, %1;" : "=r"(u) : "f"(x));
    return __uint_as_float(u);
}
__device__ __forceinline__ void mma_tf32(float* d, const uint32_t* a,
                                         const uint32_t* b) {
    asm("mma.sync.aligned.m16n8k8.row.col.f32.tf32.tf32.f32 "
        "{%0,%1,%2,%3}, {%4,%5,%6,%7}, {%8,%9}, {%0,%1,%2,%3};"
        : "+f"(d[0]), "+f"(d[1]), "+f"(d[2]), "+f"(d[3])
        : "r"(a[0]), "r"(a[1]), "r"(a[2]), "r"(a[3]), "r"(b[0]), "r"(b[1]));
}

// ---------------------------------------------------------------------------
__global__ __launch_bounds__(256)
void prep_kernel(const float* __restrict__ Wf,
                 const float* __restrict__ bf,
                 const float* __restrict__ W1,
                 const float* __restrict__ b1)
{
    int tid = threadIdx.x;
    if (tid == 0) g_total = 0;
    for (int e = tid; e < NLAT*NHID; e += 256) {
        int l = e >> 7, j = e & 127;
        float acc = 0.f;
        #pragma unroll 8
        for (int f = 0; f < NFEAT; f++)
            acc = fmaf(Wf[l*NFEAT + f], W1[(9+f)*NHID + j], acc);
        g_W1eff[e] = acc;
    }
    for (int j = tid; j < NHID; j += 256) {
        float acc = b1[j];
        #pragma unroll 8
        for (int f = 0; f < NFEAT; f++)
            acc = fmaf(bf[f], W1[(9+f)*NHID + j], acc);
        g_b1eff[j] = acc;
    }
}

// ---------------------------------------------------------------------------
// interval_kernel: one warp per ray; ballot -> contiguous [first,last], compact.
// ---------------------------------------------------------------------------
__global__ __launch_bounds__(256)
void interval_kernel(const float* __restrict__ rays_o,
                     const float* __restrict__ rays_d)
{
    int warp = (blockIdx.x*blockDim.x + threadIdx.x) >> 5;
    int lane = threadIdx.x & 31;
    if (warp >= NB_) return;
    int ray = warp;

    float ox = __ldg(&rays_o[3*ray+0]), oy = __ldg(&rays_o[3*ray+1]),
          oz = __ldg(&rays_o[3*ray+2]);
    float dx = __ldg(&rays_d[3*ray+0]), dy = __ldg(&rays_d[3*ray+1]),
          dz = __ldg(&rays_d[3*ray+2]);

    int first = -1, last = -1;
    #pragma unroll
    for (int c = 0; c < 16; c++) {
        int s = c*32 + lane;
        float z  = 0.5f + 3.0f*((float)s * (1.0f/499.0f));
        float px = fmaf(dx, z, ox), py = fmaf(dy, z, oy), pz = fmaf(dz, z, oz);
        bool act = (s < NS) &
                   (px >= -1.f) & (px <= 1.f) &
                   (py >= -1.f) & (py <= 1.f) &
                   (pz >= -1.f) & (pz <= 1.f);
        unsigned m = __ballot_sync(0xffffffffu, act);
        if (m) {
            if (first < 0) first = c*32 + (__ffs(m) - 1);
            last = c*32 + (31 - __clz(m));
        }
    }
    int cnt = (first >= 0) ? (last - first + 1) : 0;

    int off = 0;
    if (lane == 0) {
        g_slo[ray]  = first;
        g_scnt[ray] = cnt;
        if (cnt > 0) off = atomicAdd(&g_total, cnt);
    }
    off = __shfl_sync(0xffffffffu, off, 0);

    if (cnt > 0) {
        for (int s = first + lane; s <= last; s += 32)
            g_act_list[off + (s - first)] = (ray << 9) | s;
    }
}

// ---------------------------------------------------------------------------
// Kernel T: trilerp + grad, one point per thread, HIGH occupancy.
// Writes transposed inputs g_inT[k][i] (coalesced per k) + sdf at k=21.
// ---------------------------------------------------------------------------
__global__ __launch_bounds__(128, 8)
void trilerp_kernel(const float* __restrict__ rays_o,
                    const float* __restrict__ rays_d,
                    const float* __restrict__ viewdirs,
                    const float* __restrict__ grid)
{
    const int OX = RG*RG*13, OY = RG*13, OZ = 13;
    int total  = g_total;
    int gid    = blockIdx.x*blockDim.x + threadIdx.x;
    int stride = gridDim.x*blockDim.x;

    for (int i = gid; i < total; i += stride) {
        int ia = g_act_list[i];
        int r = ia >> 9, s = ia & 511;

        float z  = 0.5f + 3.0f*((float)s * (1.0f/499.0f));
        float px = fmaf(__ldg(&rays_d[3*r+0]), z, __ldg(&rays_o[3*r+0]));
        float py = fmaf(__ldg(&rays_d[3*r+1]), z, __ldg(&rays_o[3*r+1]));
        float pz = fmaf(__ldg(&rays_d[3*r+2]), z, __ldg(&rays_o[3*r+2]));

        float ux = (px + 1.f)*63.5f, uy = (py + 1.f)*63.5f, uz = (pz + 1.f)*63.5f;
        int ix = min((int)ux, 126), iy = min((int)uy, 126), iz = min((int)uz, 126);
        float fx = ux - (float)ix, fy = uy - (float)iy, fz = uz - (float)iz;
        float wx0 = 1.f-fx, wx1 = fx, wy0 = 1.f-fy, wy1 = fy,
              wz0 = 1.f-fz, wz1 = fz;

        const float* gp = grid + ((size_t)(ix*RG + iy)*RG + iz)*13;

        float vals[13];
        #pragma unroll
        for (int c = 0; c < 13; c++) vals[c] = 0.f;
        float c0a[8];
        #pragma unroll
        for (int cc = 0; cc < 8; cc++) {
            int dx = cc >> 2, dy = (cc >> 1) & 1, dz = cc & 1;
            const float* p = gp + dx*OX + dy*OY + dz*OZ;
            float w = (dx ? wx1 : wx0) * (dy ? wy1 : wy0) * (dz ? wz1 : wz0);
            float v0 = __ldg(p);
            c0a[cc] = v0;
            vals[0] = fmaf(w, v0, vals[0]);
            #pragma unroll
            for (int c = 1; c < 13; c++) vals[c] = fmaf(w, __ldg(p + c), vals[c]);
        }
        float gx = 63.5f*( wy0*wz0*(c0a[4]-c0a[0]) + wy0*wz1*(c0a[5]-c0a[1])
                         + wy1*wz0*(c0a[6]-c0a[2]) + wy1*wz1*(c0a[7]-c0a[3]) );
        float gy = 63.5f*( wx0*wz0*(c0a[2]-c0a[0]) + wx0*wz1*(c0a[3]-c0a[1])
                         + wx1*wz0*(c0a[6]-c0a[4]) + wx1*wz1*(c0a[7]-c0a[5]) );
        float gz = 63.5f*( wx0*wy0*(c0a[1]-c0a[0]) + wx0*wy1*(c0a[3]-c0a[2])
                         + wx1*wy0*(c0a[5]-c0a[4]) + wx1*wy1*(c0a[7]-c0a[6]) );

        g_inT[ 0*NPTS + i] = px;
        g_inT[ 1*NPTS + i] = py;
        g_inT[ 2*NPTS + i] = pz;
        g_inT[ 3*NPTS + i] = gx;
        g_inT[ 4*NPTS + i] = gy;
        g_inT[ 5*NPTS + i] = gz;
        g_inT[ 6*NPTS + i] = __ldg(&viewdirs[3*r+0]);
        g_inT[ 7*NPTS + i] = __ldg(&viewdirs[3*r+1]);
        g_inT[ 8*NPTS + i] = __ldg(&viewdirs[3*r+2]);
        #pragma unroll
        for (int l = 0; l < NLAT; l++)
            g_inT[(9+l)*NPTS + i] = vals[1+l];
        g_inT[21*NPTS + i] = vals[0];
    }
}

// ---------------------------------------------------------------------------
// Kernel M: tensor-core MLP, warp-split N, register-resident W fragments.
// Block 128 thr (4 warps); tile 64 pts x 128 hidden.
// Warp w owns hidden cols [32w, 32w+32) (4 n-blocks); all warps cover all
// 64 points (4 m16 atoms). W1 hi/lo fragments live in registers for the
// whole kernel; A fragments load straight from g_inT (global, L1-shared
// across warps) with in-register tf32 hi/lo split. 3-term 3xTF32 product.
// ---------------------------------------------------------------------------
__global__ __launch_bounds__(128, 3)
void mlp_kernel(const float* __restrict__ W1,
                const float* __restrict__ W2,
                const float* __restrict__ b2)
{
    __shared__ __align__(16) float sW2t[3*NHID];     // [c][j]
    __shared__ __align__(16) float sb1[NHID];
    __shared__ float sb2[4];
    __shared__ __align__(16) float po_s[4][3][MTILE]; // cross-warp partials

    int tid  = threadIdx.x;
    int w    = tid >> 5;
    int lane = tid & 31;
    int qid  = lane >> 2;   // 0..7
    int tig  = lane & 3;    // 0..3

    for (int i = tid; i < NHID; i += 128) sb1[i] = g_b1eff[i];
    for (int i = tid; i < NHID*3; i += 128) {
        int j = i / 3, c = i - 3*j;
        sW2t[c*NHID + j] = W2[i];
    }
    if (tid < 3) sb2[tid] = b2[tid];

    // one-time W1 fragment loads: warp w covers hidden [32w, 32w+32)
    float wh[3][4][2], wl[3][4][2];
    #pragma unroll
    for (int ks = 0; ks < 3; ks++) {
        #pragma unroll
        for (int nbl = 0; nbl < 4; nbl++) {
            int jb = w*32 + nbl*8 + qid;
            #pragma unroll
            for (int t = 0; t < 2; t++) {
                int k = ks*8 + tig + 4*t;
                float v = 0.f;
                if (k < 9)          v = __ldg(&W1[k*NHID + jb]);
                else if (k < NROW)  v = g_W1eff[(k-9)*NHID + jb];
                float h = tf32_rna(v);
                wh[ks][nbl][t] = h;
                wl[ks][nbl][t] = tf32_rna(v - h);
            }
        }
    }
    __syncthreads();

    int total = g_total;
    for (int base = blockIdx.x*MTILE; base < total; base += gridDim.x*MTILE) {
        float acc[4][4][4];   // [m-atom][n-block][quad-reg]
        #pragma unroll
        for (int m = 0; m < 4; m++)
            #pragma unroll
            for (int nbl = 0; nbl < 4; nbl++)
                #pragma unroll
                for (int q = 0; q < 4; q++) acc[m][nbl][q] = 0.f;

        #pragma unroll
        for (int ks = 0; ks < 3; ks++) {
            int k0 = ks*8 + tig, k1 = k0 + 4;   // k0 <= 19 always; k1 may exceed
            bool k1ok = (k1 < NROW);
            #pragma unroll
            for (int m = 0; m < 4; m++) {
                int r = base + m*16 + qid;
                bool r0ok = (r < total), r1ok = (r + 8 < total);
                float v0 = r0ok ? g_inT[k0*NPTS + r]     : 0.f;
                float v1 = r1ok ? g_inT[k0*NPTS + r + 8] : 0.f;
                float v2 = (k1ok && r0ok) ? g_inT[k1*NPTS + r]     : 0.f;
                float v3 = (k1ok && r1ok) ? g_inT[k1*NPTS + r + 8] : 0.f;
                float h0 = tf32_rna(v0), h1 = tf32_rna(v1),
                      h2 = tf32_rna(v2), h3 = tf32_rna(v3);
                uint32_t ah[4] = {__float_as_uint(h0), __float_as_uint(h1),
                                  __float_as_uint(h2), __float_as_uint(h3)};
                uint32_t al[4] = {__float_as_uint(tf32_rna(v0 - h0)),
                                  __float_as_uint(tf32_rna(v1 - h1)),
                                  __float_as_uint(tf32_rna(v2 - h2)),
                                  __float_as_uint(tf32_rna(v3 - h3))};
                #pragma unroll
                for (int nbl = 0; nbl < 4; nbl++) {
                    uint32_t bh[2] = {__float_as_uint(wh[ks][nbl][0]),
                                      __float_as_uint(wh[ks][nbl][1])};
                    uint32_t bl[2] = {__float_as_uint(wl[ks][nbl][0]),
                                      __float_as_uint(wl[ks][nbl][1])};
                    mma_tf32(acc[m][nbl], ah, bh);
                    mma_tf32(acc[m][nbl], ah, bl);
                    mma_tf32(acc[m][nbl], al, bh);
                }
            }
        }

        // epilogue: bias+relu, per-warp W2 fold -> o[m][row][c]
        float o[4][2][3];
        #pragma unroll
        for (int m = 0; m < 4; m++)
            #pragma unroll
            for (int rr = 0; rr < 2; rr++)
                #pragma unroll
                for (int c = 0; c < 3; c++) o[m][rr][c] = 0.f;

        #pragma unroll
        for (int nbl = 0; nbl < 4; nbl++) {
            int j0 = w*32 + nbl*8 + 2*tig, j1 = j0 + 1;
            float bj0 = sb1[j0], bj1 = sb1[j1];
            float w2a[3], w2b[3];
            #pragma unroll
            for (int c = 0; c < 3; c++) {
                w2a[c] = sW2t[c*NHID + j0];
                w2b[c] = sW2t[c*NHID + j1];
            }
            #pragma unroll
            for (int m = 0; m < 4; m++) {
                float h00 = fmaxf(acc[m][nbl][0] + bj0, 0.f);
                float h01 = fmaxf(acc[m][nbl][1] + bj1, 0.f);
                float h10 = fmaxf(acc[m][nbl][2] + bj0, 0.f);
                float h11 = fmaxf(acc[m][nbl][3] + bj1, 0.f);
                #pragma unroll
                for (int c = 0; c < 3; c++) {
                    o[m][0][c] = fmaf(h00, w2a[c], fmaf(h01, w2b[c], o[m][0][c]));
                    o[m][1][c] = fmaf(h10, w2a[c], fmaf(h11, w2b[c], o[m][1][c]));
                }
            }
        }
        // reduce over the 4 tig lanes within each quad
        #pragma unroll
        for (int off = 1; off <= 2; off <<= 1)
            #pragma unroll
            for (int m = 0; m < 4; m++)
                #pragma unroll
                for (int rr = 0; rr < 2; rr++)
                    #pragma unroll
                    for (int c = 0; c < 3; c++)
                        o[m][rr][c] += __shfl_xor_sync(0xffffffffu, o[m][rr][c], off);

        __syncthreads();   // previous tile's po_s reads complete
        if (tig == 0) {
            #pragma unroll
            for (int m = 0; m < 4; m++)
                #pragma unroll
                for (int rr = 0; rr < 2; rr++) {
                    int p = m*16 + qid + 8*rr;
                    #pragma unroll
                    for (int c = 0; c < 3; c++)
                        po_s[w][c][p] = o[m][rr][c];
                }
        }
        __syncthreads();

        if (tid < MTILE) {
            int i = base + tid;
            if (i < total) {
                float oc[3];
                #pragma unroll
                for (int c = 0; c < 3; c++)
                    oc[c] = po_s[0][c][tid] + po_s[1][c][tid]
                          + po_s[2][c][tid] + po_s[3][c][tid] + sb2[c];
                float sdf = __ldg(&g_inT[21*NPTS + i]);
                int pa = g_act_list[i];
                g_rgbs[(pa >> 9)*NS + (pa & 511)] =
                    make_float4(1.f/(1.f + expf(-oc[0])),
                                1.f/(1.f + expf(-oc[1])),
                                1.f/(1.f + expf(-oc[2])), sdf);
            }
        }
    }
}

// ---------------------------------------------------------------------------
// Kernel B: per-ray transmittance scan. One warp (=one block) per ray.
// ---------------------------------------------------------------------------
__global__ __launch_bounds__(32)
void ray_kernel(const float* __restrict__ rays_d,
                const float* __restrict__ beta_p,
                float* __restrict__ out)
{
    int ray  = blockIdx.x;
    int lane = threadIdx.x;

    float be    = fabsf(__ldg(beta_p)) + 1e-4f;
    float inv_b = 1.0f / be;
    float d0 = __ldg(&rays_d[3*ray+0]);
    float d1 = __ldg(&rays_d[3*ray+1]);
    float d2 = __ldg(&rays_d[3*ray+2]);
    float dn = sqrtf(d0*d0 + d1*d1 + d2*d2);

    int slo = g_slo[ray];
    int scnt = g_scnt[ray];
    int shi = slo + scnt;

    const float4* vp = g_rgbs + (size_t)ray*NS;
    const float dist = 3.0f/499.0f;

    float4 v[16];
    #pragma unroll
    for (int c = 0; c < 16; c++) {
        int s = c*32 + lane;
        bool in = (scnt > 0) & (s >= slo) & (s < shi) & (s < NS);
        v[c] = in ? __ldg(&vp[s]) : make_float4(0.f, 0.f, 0.f, 100.f);
    }

    float fe[16];
    #pragma unroll
    for (int c = 0; c < 16; c++) {
        float sdf = v[c].w;
        float as  = fabsf(sdf);
        float sg  = (sdf > 0.f) ? 1.f : ((sdf < 0.f) ? -1.f : 0.f);
        float dens = inv_b * (0.5f + 0.5f*sg*expm1f(-as*inv_b));
        fe[c] = dist * dens;
    }

    float inc[16];
    #pragma unroll
    for (int c = 0; c < 16; c++) {
        float x = fe[c];
        #pragma unroll
        for (int o = 1; o < 32; o <<= 1) {
            float n = __shfl_up_sync(0xffffffffu, x, o);
            if (lane >= o) x += n;
        }
        inc[c] = x;
    }

    float carry = 0.f, r0 = 0.f, r1 = 0.f, r2 = 0.f, dep = 0.f;
    #pragma unroll
    for (int c = 0; c < 16; c++) {
        float excl  = carry + (inc[c] - fe[c]);
        float T     = expf(-excl);
        float alpha = 1.f - expf(-fe[c]);
        float w     = alpha * T;
        int   s     = c*32 + lane;
        float zs    = 0.5f + 3.0f*((float)s * (1.0f/499.0f));
        if (s < NS) {
            r0  += w * v[c].x;
            r1  += w * v[c].y;
            r2  += w * v[c].z;
            dep += w * zs * dn;
        }
        carry += __shfl_sync(0xffffffffu, inc[c], 31);
    }

    #pragma unroll
    for (int o = 16; o > 0; o >>= 1) {
        r0  += __shfl_xor_sync(0xffffffffu, r0,  o);
        r1  += __shfl_xor_sync(0xffffffffu, r1,  o);
        r2  += __shfl_xor_sync(0xffffffffu, r2,  o);
        dep += __shfl_xor_sync(0xffffffffu, dep, o);
    }
    if (lane == 0) {
        out[3*ray+0]     = r0;
        out[3*ray+1]     = r1;
        out[3*ray+2]     = r2;
        out[3*NB_ + ray] = dep;
    }
}

// ---------------------------------------------------------------------------
extern "C" void kernel_launch(void* const* d_in, const int* in_sizes, int n_in,
                              void* d_out, int out_size)
{
    const float* rays_o   = (const float*)d_in[0];
    const float* rays_d   = (const float*)d_in[1];
    const float* viewdirs = (const float*)d_in[2];
    const float* grid     = (const float*)d_in[3];
    const float* Wf       = (const float*)d_in[4];
    const float* bf       = (const float*)d_in[5];
    const float* W1       = (const float*)d_in[6];
    const float* b1       = (const float*)d_in[7];
    const float* W2       = (const float*)d_in[8];
    const float* b2       = (const float*)d_in[9];
    const float* beta     = (const float*)d_in[10];

    // ncu captures our 0-based launch index 3 -> mlp_kernel there.
    prep_kernel<<<1, 256>>>(Wf, bf, W1, b1);                 // resets g_total
    interval_kernel<<<NB_/8, 256>>>(rays_o, rays_d);
    trilerp_kernel<<<1184, 128>>>(rays_o, rays_d, viewdirs, grid);
    mlp_kernel<<<740, 128>>>(W1, W2, b2);
    ray_kernel<<<NB_, 32>>>(rays_d, beta, (float*)d_out);
}